// round 15
// baseline (speedup 1.0000x reference)
#include <cuda_runtime.h>
#include <cuda_bf16.h>
#include <cstdint>

// VQ nearest-code lookup via mma.sync bf16 3-pass fp32 emulation (2-term splits).
// M=32 rows/warp (2 M-tiles amortize each B fragment), atomic chunk queue,
// double-buffered ldmatrix B, SPLIT accumulator chains (D, S1, S2 per M-tile).
// Packed-key top-3 + exact fp32 recheck. x reloaded in epilogue.
// x:   [32, 64, 64, 64] fp32 -> row r = b*4096 + n; elem (r,c) at x[b*262144 + c*4096 + n]
// emb: [512, 64] fp32
// out: flat [131072, 64] fp32 row-major.

#define THREADS  384
#define NCHUNKS  4096          // 131072 rows / 32 rows per warp-chunk
#define GRIDSZ   148
#define B_TERM   65536         // one bf16 codebook term: 512 rows x 128B
#define SM_ESQ   (2 * B_TERM)
#define SMEM_TOTAL (2 * B_TERM + 2048)
#define BIAS     256.0f
// E_max ~ 1e-2 (3-pass emulation worst case) + 3.9e-3 key truncation.
// Threshold must exceed 2*E_max; 4e-2 gives margin. (Same as R11/R13/R14.)
#define GAP_THRESH 4.0e-2f

__device__ unsigned int g_chunk_ctr;

__global__ void vq_init_kernel() { g_chunk_ctr = 0u; }

__device__ __forceinline__ uint32_t smem_u32(const void* p) {
    uint32_t a;
    asm("{ .reg .u64 t; cvta.to.shared.u64 t, %1; cvt.u32.u64 %0, t; }" : "=r"(a) : "l"(p));
    return a;
}

__device__ __forceinline__ void mma16816(float& d0, float& d1, float& d2, float& d3,
                                         uint32_t a0, uint32_t a1, uint32_t a2, uint32_t a3,
                                         uint32_t b0, uint32_t b1) {
    asm("mma.sync.aligned.m16n8k16.row.col.f32.bf16.bf16.f32 "
        "{%0,%1,%2,%3}, {%4,%5,%6,%7}, {%8,%9}, {%0,%1,%2,%3};"
        : "+f"(d0), "+f"(d1), "+f"(d2), "+f"(d3)
        : "r"(a0), "r"(a1), "r"(a2), "r"(a3), "r"(b0), "r"(b1));
}

__device__ __forceinline__ void ldm4(uint32_t& r0, uint32_t& r1, uint32_t& r2, uint32_t& r3,
                                     uint32_t addr) {
    asm volatile("ldmatrix.sync.aligned.m8n8.x4.shared.b16 {%0,%1,%2,%3}, [%4];"
                 : "=r"(r0), "=r"(r1), "=r"(r2), "=r"(r3) : "r"(addr));
}

// Exact 2-term bf16 split (round-and-subtract residual exact in fp32).
__device__ __forceinline__ void split2(float v, uint16_t& h, uint16_t& l) {
    __nv_bfloat16 bh = __float2bfloat16_rn(v);
    float r = v - __bfloat162float(bh);
    __nv_bfloat16 bl = __float2bfloat16_rn(r);
    h = __bfloat16_as_ushort(bh); l = __bfloat16_as_ushort(bl);
}

// Packed-key top-3 insert: pure min/max sorting network (keeps B1<=B2<=B3).
#define INSK(k_, B1_, B2_, B3_) do {                          \
    uint32_t _t1 = max((B1_), (k_)); B1_ = min((B1_), (k_));  \
    uint32_t _t2 = max((B2_), _t1);  B2_ = min((B2_), _t1);   \
    B3_ = min((B3_), _t2);                                    \
} while (0)

// Lexicographic insert (tie -> smaller index), for cross-lane merges.
#define INS3(m_, n_, B1_, I1_, B2_, I2_, B3_, I3_) do {                   \
    bool _l1 = ((m_) < (B1_)) || ((m_) == (B1_) && (n_) < (I1_));         \
    bool _l2 = ((m_) < (B2_)) || ((m_) == (B2_) && (n_) < (I2_));         \
    bool _l3 = ((m_) < (B3_)) || ((m_) == (B3_) && (n_) < (I3_));         \
    B3_ = _l2 ? (B2_) : (_l3 ? (m_) : (B3_));                             \
    I3_ = _l2 ? (I2_) : (_l3 ? (n_) : (I3_));                             \
    B2_ = _l1 ? (B1_) : (_l2 ? (m_) : (B2_));                             \
    I2_ = _l1 ? (I1_) : (_l2 ? (n_) : (I2_));                             \
    B1_ = _l1 ? (m_) : (B1_);                                             \
    I1_ = _l1 ? (n_) : (I1_);                                             \
} while (0)

#define MRG3(off, B1_, I1_, B2_, I2_, B3_, I3_) do {                      \
    float _o1 = __shfl_xor_sync(0xffffffffu, B1_, off);                   \
    int   _j1 = __shfl_xor_sync(0xffffffffu, I1_, off);                   \
    float _o2 = __shfl_xor_sync(0xffffffffu, B2_, off);                   \
    int   _j2 = __shfl_xor_sync(0xffffffffu, I2_, off);                   \
    float _o3 = __shfl_xor_sync(0xffffffffu, B3_, off);                   \
    int   _j3 = __shfl_xor_sync(0xffffffffu, I3_, off);                   \
    INS3(_o1, _j1, B1_, I1_, B2_, I2_, B3_, I3_);                         \
    INS3(_o2, _j2, B1_, I1_, B2_, I2_, B3_, I3_);                         \
    INS3(_o3, _j3, B1_, I1_, B2_, I2_, B3_, I3_);                         \
} while (0)

// Exact fp32 dot of row (xr, 16 vals, mma layout) with code c; quad-reduced.
__device__ __forceinline__ float exact_dot(const float2* __restrict__ e2p,
                                           int c, const float* xr, int tig) {
    float s = 0.0f;
    #pragma unroll
    for (int ks = 0; ks < 4; ks++) {
        float2 e0 = __ldg(&e2p[c * 32 + ks * 8 + tig]);
        float2 e1 = __ldg(&e2p[c * 32 + ks * 8 + tig + 4]);
        s = fmaf(xr[ks*4+0], e0.x, s); s = fmaf(xr[ks*4+1], e0.y, s);
        s = fmaf(xr[ks*4+2], e1.x, s); s = fmaf(xr[ks*4+3], e1.y, s);
    }
    s += __shfl_xor_sync(0xffffffffu, s, 1);
    s += __shfl_xor_sync(0xffffffffu, s, 2);
    return s;
}

// Unpack a packed key: biased truncated value + global code index.
__device__ __forceinline__ void unpack_key(uint32_t key, int tig, float& v, int& n) {
    v = __uint_as_float(key & 0xFFFFFF80u);
    const int l = key & 127;
    n = (l >> 1) * 8 + 2 * tig + (l & 1);
}

__global__ void __launch_bounds__(THREADS, 1)
vq_mma_kernel(const float* __restrict__ x, const float* __restrict__ emb,
              float* __restrict__ out)
{
    extern __shared__ char sm[];
    float* esqb = (float*)(sm + SM_ESQ);      // e_sq + BIAS
    const float2* esqb2 = (const float2*)esqb;
    const uint32_t sbase = smem_u32(sm);

    const int tid  = threadIdx.x;
    const int lane = tid & 31;
    const int g    = lane >> 2;     // row within 8
    const int tig  = lane & 3;      // thread in group

    // ---- Stage codebook: 2 bf16 terms, ldmatrix XOR swizzle ----
    for (int idx = tid; idx < 512 * 64; idx += THREADS) {
        const int n = idx >> 6, k = idx & 63;
        uint16_t h, l;
        split2(__ldg(&emb[idx]), h, l);
        const uint32_t o = (uint32_t)(n * 128 + ((((k >> 3) ^ (n & 7))) << 4) + ((k & 7) << 1));
        *(uint16_t*)(sm + o)          = h;
        *(uint16_t*)(sm + B_TERM + o) = l;
    }
    for (int n = tid; n < 512; n += THREADS) {
        float s = 0.0f;
        #pragma unroll
        for (int k = 0; k < 64; k++) { float v = __ldg(&emb[n * 64 + k]); s = fmaf(v, v, s); }
        esqb[n] = s + BIAS;
    }
    __syncthreads();

    // ldmatrix base addresses: term t, k-pair p.
    const int l7 = lane & 7, sel = lane >> 3;
    uint32_t lmb[2][2];
    #pragma unroll
    for (int t = 0; t < 2; t++)
        #pragma unroll
        for (int p = 0; p < 2; p++)
            lmb[t][p] = sbase + t * B_TERM + l7 * 128 + (((4 * p + sel) ^ l7) << 4);

    const float2* e2p = (const float2*)emb;
    float2* o2 = (float2*)out;

    // ---- Warp-autonomous 32-row chunks from the global atomic queue ----
    while (true) {
        unsigned int chunk;
        if (lane == 0) chunk = atomicAdd(&g_chunk_ctr, 1u);
        chunk = __shfl_sync(0xffffffffu, chunk, 0);
        if (chunk >= NCHUNKS) break;

        const int rbase = (int)chunk * 32;              // all 32 rows in same batch
        const int bb    = rbase >> 12;
        const float* xb = x + (size_t)bb * 262144;

        // Build A fragments for 2 M-tiles; x fp32 not retained (reloaded later).
        uint32_t A1[32], A2[32];
        #pragma unroll
        for (int mt = 0; mt < 2; mt++) {
            const int ng = (rbase + 16 * mt + g) & 4095;
            #pragma unroll
            for (int ks = 0; ks < 4; ks++) {
                uint16_t h0, l0, h1, l1;
                float v0, v1;
                v0 = __ldg(&xb[(size_t)(ks*16 + tig*2 + 0) * 4096 + ng]);
                v1 = __ldg(&xb[(size_t)(ks*16 + tig*2 + 1) * 4096 + ng]);
                split2(v0, h0, l0); split2(v1, h1, l1);
                A1[mt*16 + ks*4 + 0] = (uint32_t)h0 | ((uint32_t)h1 << 16);
                A2[mt*16 + ks*4 + 0] = (uint32_t)l0 | ((uint32_t)l1 << 16);
                v0 = __ldg(&xb[(size_t)(ks*16 + tig*2 + 0) * 4096 + ng + 8]);
                v1 = __ldg(&xb[(size_t)(ks*16 + tig*2 + 1) * 4096 + ng + 8]);
                split2(v0, h0, l0); split2(v1, h1, l1);
                A1[mt*16 + ks*4 + 1] = (uint32_t)h0 | ((uint32_t)h1 << 16);
                A2[mt*16 + ks*4 + 1] = (uint32_t)l0 | ((uint32_t)l1 << 16);
                v0 = __ldg(&xb[(size_t)(ks*16 + tig*2 + 8) * 4096 + ng]);
                v1 = __ldg(&xb[(size_t)(ks*16 + tig*2 + 9) * 4096 + ng]);
                split2(v0, h0, l0); split2(v1, h1, l1);
                A1[mt*16 + ks*4 + 2] = (uint32_t)h0 | ((uint32_t)h1 << 16);
                A2[mt*16 + ks*4 + 2] = (uint32_t)l0 | ((uint32_t)l1 << 16);
                v0 = __ldg(&xb[(size_t)(ks*16 + tig*2 + 8) * 4096 + ng + 8]);
                v1 = __ldg(&xb[(size_t)(ks*16 + tig*2 + 9) * 4096 + ng + 8]);
                split2(v0, h0, l0); split2(v1, h1, l1);
                A1[mt*16 + ks*4 + 3] = (uint32_t)h0 | ((uint32_t)h1 << 16);
                A2[mt*16 + ks*4 + 3] = (uint32_t)l0 | ((uint32_t)l1 << 16);
            }
        }

        uint32_t K1[4], K2[4], K3[4];
        #pragma unroll
        for (int q = 0; q < 4; q++) { K1[q] = 0xFFFFFFFFu; K2[q] = 0xFFFFFFFFu; K3[q] = 0xFFFFFFFFu; }

        // Ping-pong double-buffered B fragments; 2 code-blocks per iteration.
        uint32_t B0h[8], B0l[8], B1h[8], B1l[8];
        ldm4(B0h[0], B0h[1], B0h[2], B0h[3], lmb[0][0]);
        ldm4(B0h[4], B0h[5], B0h[6], B0h[7], lmb[0][1]);
        ldm4(B0l[0], B0l[1], B0l[2], B0l[3], lmb[1][0]);
        ldm4(B0l[4], B0l[5], B0l[6], B0l[7], lmb[1][1]);

        // Consume one 8-code block: 24 MMAs over 6 independent chains
        // (D, S1, S2 per M-tile), then fold into packed-key top-3.
        #define CONSUME_BLOCK(Bh_, Bl_, NC_) do {                                             \
            float D0[4]={0,0,0,0}, S1a[4]={0,0,0,0}, S2a[4]={0,0,0,0};                        \
            float D1[4]={0,0,0,0}, S1b[4]={0,0,0,0}, S2b[4]={0,0,0,0};                        \
            _Pragma("unroll")                                                                 \
            for (int ks = 0; ks < 4; ks++) {                                                  \
                const uint32_t bh0 = Bh_[2*ks], bh1 = Bh_[2*ks+1];                            \
                const uint32_t bl0 = Bl_[2*ks], bl1 = Bl_[2*ks+1];                            \
                mma16816(S1a[0],S1a[1],S1a[2],S1a[3], A2[ks*4+0],A2[ks*4+1],A2[ks*4+2],A2[ks*4+3], bh0,bh1); \
                mma16816(S1b[0],S1b[1],S1b[2],S1b[3], A2[16+ks*4+0],A2[16+ks*4+1],A2[16+ks*4+2],A2[16+ks*4+3], bh0,bh1); \
                mma16816(D0[0],D0[1],D0[2],D0[3], A1[ks*4+0],A1[ks*4+1],A1[ks*4+2],A1[ks*4+3], bh0,bh1); \
                mma16816(D1[0],D1[1],D1[2],D1[3], A1[16+ks*4+0],A1[16+ks*4+1],A1[16+ks*4+2],A1[16+ks*4+3], bh0,bh1); \
                mma16816(S2a[0],S2a[1],S2a[2],S2a[3], A1[ks*4+0],A1[ks*4+1],A1[ks*4+2],A1[ks*4+3], bl0,bl1); \
                mma16816(S2b[0],S2b[1],S2b[2],S2b[3], A1[16+ks*4+0],A1[16+ks*4+1],A1[16+ks*4+2],A1[16+ks*4+3], bl0,bl1); \
            }                                                                                 \
            const float2 sv = esqb2[(NC_) * 4 + tig];                                         \
            const uint32_t lc = (uint32_t)(NC_) << 1;                                         \
            uint32_t kk;                                                                      \
            kk = (__float_as_uint(fmaf(-2.0f, D0[0] + S1a[0] + S2a[0], sv.x)) & 0xFFFFFF80u) | lc;       \
            INSK(kk, K1[0], K2[0], K3[0]);                                                    \
            kk = (__float_as_uint(fmaf(-2.0f, D0[1] + S1a[1] + S2a[1], sv.y)) & 0xFFFFFF80u) | (lc + 1); \
            INSK(kk, K1[0], K2[0], K3[0]);                                                    \
            kk = (__float_as_uint(fmaf(-2.0f, D0[2] + S1a[2] + S2a[2], sv.x)) & 0xFFFFFF80u) | lc;       \
            INSK(kk, K1[1], K2[1], K3[1]);                                                    \
            kk = (__float_as_uint(fmaf(-2.0f, D0[3] + S1a[3] + S2a[3], sv.y)) & 0xFFFFFF80u) | (lc + 1); \
            INSK(kk, K1[1], K2[1], K3[1]);                                                    \
            kk = (__float_as_uint(fmaf(-2.0f, D1[0] + S1b[0] + S2b[0], sv.x)) & 0xFFFFFF80u) | lc;       \
            INSK(kk, K1[2], K2[2], K3[2]);                                                    \
            kk = (__float_as_uint(fmaf(-2.0f, D1[1] + S1b[1] + S2b[1], sv.y)) & 0xFFFFFF80u) | (lc + 1); \
            INSK(kk, K1[2], K2[2], K3[2]);                                                    \
            kk = (__float_as_uint(fmaf(-2.0f, D1[2] + S1b[2] + S2b[2], sv.x)) & 0xFFFFFF80u) | lc;       \
            INSK(kk, K1[3], K2[3], K3[3]);                                                    \
            kk = (__float_as_uint(fmaf(-2.0f, D1[3] + S1b[3] + S2b[3], sv.y)) & 0xFFFFFF80u) | (lc + 1); \
            INSK(kk, K1[3], K2[3], K3[3]);                                                    \
        } while (0)

        #pragma unroll 1
        for (int nc = 0; nc < 64; nc += 2) {
            // Prefetch block nc+1 into B1 (hides under B0's MMAs).
            {
                const uint32_t co = (uint32_t)(nc + 1) << 10;
                ldm4(B1h[0], B1h[1], B1h[2], B1h[3], lmb[0][0] + co);
                ldm4(B1h[4], B1h[5], B1h[6], B1h[7], lmb[0][1] + co);
                ldm4(B1l[0], B1l[1], B1l[2], B1l[3], lmb[1][0] + co);
                ldm4(B1l[4], B1l[5], B1l[6], B1l[7], lmb[1][1] + co);
            }
            CONSUME_BLOCK(B0h, B0l, nc);
            // Prefetch block nc+2 into B0 (wraps on last iter; harmless).
            {
                const uint32_t co = (uint32_t)((nc + 2) & 63) << 10;
                ldm4(B0h[0], B0h[1], B0h[2], B0h[3], lmb[0][0] + co);
                ldm4(B0h[4], B0h[5], B0h[6], B0h[7], lmb[0][1] + co);
                ldm4(B0l[0], B0l[1], B0l[2], B0l[3], lmb[1][0] + co);
                ldm4(B0l[4], B0l[5], B0l[6], B0l[7], lmb[1][1] + co);
            }
            CONSUME_BLOCK(B1h, B1l, nc + 1);
        }
        #undef CONSUME_BLOCK

        // Epilogue: per row-fragment q (row = rbase + 16*(q>>1) + 8*(q&1) + g).
        #pragma unroll
        for (int q = 0; q < 4; q++) {
            const int row = rbase + 16 * (q >> 1) + 8 * (q & 1) + g;
            const int nl  = row & 4095;

            float xr[16];
            #pragma unroll
            for (int ks = 0; ks < 4; ks++) {
                xr[ks*4+0] = __ldg(&xb[(size_t)(ks*16 + tig*2 + 0) * 4096 + nl]);
                xr[ks*4+1] = __ldg(&xb[(size_t)(ks*16 + tig*2 + 1) * 4096 + nl]);
                xr[ks*4+2] = __ldg(&xb[(size_t)(ks*16 + tig*2 + 8) * 4096 + nl]);
                xr[ks*4+3] = __ldg(&xb[(size_t)(ks*16 + tig*2 + 9) * 4096 + nl]);
            }

            float b1, b2, b3; int i1, i2, i3;
            unpack_key(K1[q], tig, b1, i1);
            unpack_key(K2[q], tig, b2, i2);
            unpack_key(K3[q], tig, b3, i3);
            MRG3(1, b1, i1, b2, i2, b3, i3);
            MRG3(2, b1, i1, b2, i2, b3, i3);

            const bool tr = (b2 - b1) < GAP_THRESH;
            if (__ballot_sync(0xffffffffu, tr)) {
                const float dA = fmaf(-2.0f, exact_dot(e2p, i1, xr, tig), esqb[i1]);
                const float dB = fmaf(-2.0f, exact_dot(e2p, i2, xr, tig), esqb[i2]);
                const float dC = fmaf(-2.0f, exact_dot(e2p, i3, xr, tig), esqb[i3]);
                int bi = i1; float bd = dA;
                if ((dB < bd) || (dB == bd && i2 < bi)) { bd = dB; bi = i2; }
                if ((dC < bd) || (dC == bd && i3 < bi)) { bd = dC; bi = i3; }
                if (tr) i1 = bi;
            }

            // Straight-through output: out = x + (e - x), fp32.
            const size_t ob = (size_t)row * 32;
            #pragma unroll
            for (int ks = 0; ks < 4; ks++) {
                const float2 e0 = __ldg(&e2p[i1 * 32 + ks * 8 + tig]);
                const float2 e1 = __ldg(&e2p[i1 * 32 + ks * 8 + tig + 4]);
                float2 v;
                v.x = xr[ks*4+0] + (e0.x - xr[ks*4+0]);
                v.y = xr[ks*4+1] + (e0.y - xr[ks*4+1]);
                o2[ob + ks * 8 + tig] = v;
                v.x = xr[ks*4+2] + (e1.x - xr[ks*4+2]);
                v.y = xr[ks*4+3] + (e1.y - xr[ks*4+3]);
                o2[ob + ks * 8 + tig + 4] = v;
            }
        }
    }
}

extern "C" void kernel_launch(void* const* d_in, const int* in_sizes, int n_in,
                              void* d_out, int out_size)
{
    const float* x   = (const float*)d_in[0];
    const float* emb = (const float*)d_in[1];
    float* out = (float*)d_out;

    cudaFuncSetAttribute(vq_mma_kernel,
                         cudaFuncAttributeMaxDynamicSharedMemorySize, SMEM_TOTAL);
    vq_init_kernel<<<1, 1>>>();
    vq_mma_kernel<<<GRIDSZ, THREADS, SMEM_TOTAL>>>(x, emb, out);
}

// round 16
// speedup vs baseline: 1.1153x; 1.1153x over previous
#include <cuda_runtime.h>
#include <cuda_bf16.h>
#include <cstdint>

// VQ nearest-code lookup via mma.sync bf16 3-pass fp32 emulation (2-term splits).
// M=16 rows/warp, atomic chunk queue, double-buffered ldmatrix B, SPLIT
// accumulator chains (D, S1, S2 -> max chain depth 4). 448 threads/CTA so
// 2072 warps divide the 8192 chunks with ~1% makespan tail.
// Packed-key top-3 + exact fp32 recheck.
// x:   [32, 64, 64, 64] fp32 -> row r = b*4096 + n; elem (r,c) at x[b*262144 + c*4096 + n]
// emb: [512, 64] fp32
// out: flat [131072, 64] fp32 row-major.

#define THREADS  448
#define NCHUNKS  8192          // 131072 rows / 16 rows per warp-chunk
#define GRIDSZ   148
#define B_TERM   65536         // one bf16 codebook term: 512 rows x 128B
#define SM_ESQ   (2 * B_TERM)
#define SMEM_TOTAL (2 * B_TERM + 2048)
#define BIAS     256.0f
// E_max ~ 1e-2 (3-pass emulation worst case) + 3.9e-3 key truncation.
// Threshold must exceed 2*E_max; 4e-2 gives margin. (Same as R11/R13/R14.)
#define GAP_THRESH 4.0e-2f

__device__ unsigned int g_chunk_ctr;

__global__ void vq_init_kernel() { g_chunk_ctr = 0u; }

__device__ __forceinline__ uint32_t smem_u32(const void* p) {
    uint32_t a;
    asm("{ .reg .u64 t; cvta.to.shared.u64 t, %1; cvt.u32.u64 %0, t; }" : "=r"(a) : "l"(p));
    return a;
}

__device__ __forceinline__ void mma16816(float& d0, float& d1, float& d2, float& d3,
                                         uint32_t a0, uint32_t a1, uint32_t a2, uint32_t a3,
                                         uint32_t b0, uint32_t b1) {
    asm("mma.sync.aligned.m16n8k16.row.col.f32.bf16.bf16.f32 "
        "{%0,%1,%2,%3}, {%4,%5,%6,%7}, {%8,%9}, {%0,%1,%2,%3};"
        : "+f"(d0), "+f"(d1), "+f"(d2), "+f"(d3)
        : "r"(a0), "r"(a1), "r"(a2), "r"(a3), "r"(b0), "r"(b1));
}

__device__ __forceinline__ void ldm4(uint32_t& r0, uint32_t& r1, uint32_t& r2, uint32_t& r3,
                                     uint32_t addr) {
    asm volatile("ldmatrix.sync.aligned.m8n8.x4.shared.b16 {%0,%1,%2,%3}, [%4];"
                 : "=r"(r0), "=r"(r1), "=r"(r2), "=r"(r3) : "r"(addr));
}

// Exact 2-term bf16 split (round-and-subtract residual exact in fp32).
__device__ __forceinline__ void split2(float v, uint16_t& h, uint16_t& l) {
    __nv_bfloat16 bh = __float2bfloat16_rn(v);
    float r = v - __bfloat162float(bh);
    __nv_bfloat16 bl = __float2bfloat16_rn(r);
    h = __bfloat16_as_ushort(bh); l = __bfloat16_as_ushort(bl);
}

// Packed-key top-3 insert: pure min/max sorting network (keeps B1<=B2<=B3).
#define INSK(k_, B1_, B2_, B3_) do {                          \
    uint32_t _t1 = max((B1_), (k_)); B1_ = min((B1_), (k_));  \
    uint32_t _t2 = max((B2_), _t1);  B2_ = min((B2_), _t1);   \
    B3_ = min((B3_), _t2);                                    \
} while (0)

// Lexicographic insert (tie -> smaller index), for cross-lane merges.
#define INS3(m_, n_, B1_, I1_, B2_, I2_, B3_, I3_) do {                   \
    bool _l1 = ((m_) < (B1_)) || ((m_) == (B1_) && (n_) < (I1_));         \
    bool _l2 = ((m_) < (B2_)) || ((m_) == (B2_) && (n_) < (I2_));         \
    bool _l3 = ((m_) < (B3_)) || ((m_) == (B3_) && (n_) < (I3_));         \
    B3_ = _l2 ? (B2_) : (_l3 ? (m_) : (B3_));                             \
    I3_ = _l2 ? (I2_) : (_l3 ? (n_) : (I3_));                             \
    B2_ = _l1 ? (B1_) : (_l2 ? (m_) : (B2_));                             \
    I2_ = _l1 ? (I1_) : (_l2 ? (n_) : (I2_));                             \
    B1_ = _l1 ? (m_) : (B1_);                                             \
    I1_ = _l1 ? (n_) : (I1_);                                             \
} while (0)

#define MRG3(off, B1_, I1_, B2_, I2_, B3_, I3_) do {                      \
    float _o1 = __shfl_xor_sync(0xffffffffu, B1_, off);                   \
    int   _j1 = __shfl_xor_sync(0xffffffffu, I1_, off);                   \
    float _o2 = __shfl_xor_sync(0xffffffffu, B2_, off);                   \
    int   _j2 = __shfl_xor_sync(0xffffffffu, I2_, off);                   \
    float _o3 = __shfl_xor_sync(0xffffffffu, B3_, off);                   \
    int   _j3 = __shfl_xor_sync(0xffffffffu, I3_, off);                   \
    INS3(_o1, _j1, B1_, I1_, B2_, I2_, B3_, I3_);                         \
    INS3(_o2, _j2, B1_, I1_, B2_, I2_, B3_, I3_);                         \
    INS3(_o3, _j3, B1_, I1_, B2_, I2_, B3_, I3_);                         \
} while (0)

// Exact fp32 dot of row (xr, 16 vals, mma layout) with code c; quad-reduced.
__device__ __forceinline__ float exact_dot(const float2* __restrict__ e2p,
                                           int c, const float* xr, int tig) {
    float s = 0.0f;
    #pragma unroll
    for (int ks = 0; ks < 4; ks++) {
        float2 e0 = __ldg(&e2p[c * 32 + ks * 8 + tig]);
        float2 e1 = __ldg(&e2p[c * 32 + ks * 8 + tig + 4]);
        s = fmaf(xr[ks*4+0], e0.x, s); s = fmaf(xr[ks*4+1], e0.y, s);
        s = fmaf(xr[ks*4+2], e1.x, s); s = fmaf(xr[ks*4+3], e1.y, s);
    }
    s += __shfl_xor_sync(0xffffffffu, s, 1);
    s += __shfl_xor_sync(0xffffffffu, s, 2);
    return s;
}

// Unpack a packed key: biased truncated value + global code index.
__device__ __forceinline__ void unpack_key(uint32_t key, int tig, float& v, int& n) {
    v = __uint_as_float(key & 0xFFFFFF80u);
    const int l = key & 127;
    n = (l >> 1) * 8 + 2 * tig + (l & 1);
}

__global__ void __launch_bounds__(THREADS, 1)
vq_mma_kernel(const float* __restrict__ x, const float* __restrict__ emb,
              float* __restrict__ out)
{
    extern __shared__ char sm[];
    float* esqb = (float*)(sm + SM_ESQ);      // e_sq + BIAS
    const float2* esqb2 = (const float2*)esqb;
    const uint32_t sbase = smem_u32(sm);

    const int tid  = threadIdx.x;
    const int lane = tid & 31;
    const int g    = lane >> 2;     // row within 8
    const int tig  = lane & 3;      // thread in group

    // ---- Stage codebook: 2 bf16 terms, ldmatrix XOR swizzle ----
    for (int idx = tid; idx < 512 * 64; idx += THREADS) {
        const int n = idx >> 6, k = idx & 63;
        uint16_t h, l;
        split2(__ldg(&emb[idx]), h, l);
        const uint32_t o = (uint32_t)(n * 128 + ((((k >> 3) ^ (n & 7))) << 4) + ((k & 7) << 1));
        *(uint16_t*)(sm + o)          = h;
        *(uint16_t*)(sm + B_TERM + o) = l;
    }
    for (int n = tid; n < 512; n += THREADS) {
        float s = 0.0f;
        #pragma unroll
        for (int k = 0; k < 64; k++) { float v = __ldg(&emb[n * 64 + k]); s = fmaf(v, v, s); }
        esqb[n] = s + BIAS;
    }
    __syncthreads();

    // ldmatrix base addresses: term t, k-pair p.
    const int l7 = lane & 7, sel = lane >> 3;
    uint32_t lmb[2][2];
    #pragma unroll
    for (int t = 0; t < 2; t++)
        #pragma unroll
        for (int p = 0; p < 2; p++)
            lmb[t][p] = sbase + t * B_TERM + l7 * 128 + (((4 * p + sel) ^ l7) << 4);

    const float2* e2p = (const float2*)emb;
    float2* o2 = (float2*)out;

    // ---- Warp-autonomous chunks from a global atomic queue (no tail) ----
    while (true) {
        unsigned int chunk;
        if (lane == 0) chunk = atomicAdd(&g_chunk_ctr, 1u);
        chunk = __shfl_sync(0xffffffffu, chunk, 0);
        if (chunk >= NCHUNKS) break;

        const int rlo = (int)chunk * 16 + g;            // frag rows: rlo, rlo+8
        const int bb  = rlo >> 12;
        const int nlo = rlo & 4095;
        const float* xb = x + (size_t)bb * 262144;

        // Build A fragments (2 terms x 4 ksteps x 4 regs); x fp32 not retained.
        uint32_t A1[16], A2[16];
        #pragma unroll
        for (int ks = 0; ks < 4; ks++) {
            uint16_t h0, l0, h1, l1;
            float v0, v1;
            v0 = __ldg(&xb[(size_t)(ks*16 + tig*2 + 0) * 4096 + nlo]);
            v1 = __ldg(&xb[(size_t)(ks*16 + tig*2 + 1) * 4096 + nlo]);
            split2(v0, h0, l0); split2(v1, h1, l1);
            A1[ks*4+0] = (uint32_t)h0 | ((uint32_t)h1 << 16);
            A2[ks*4+0] = (uint32_t)l0 | ((uint32_t)l1 << 16);
            v0 = __ldg(&xb[(size_t)(ks*16 + tig*2 + 0) * 4096 + nlo + 8]);
            v1 = __ldg(&xb[(size_t)(ks*16 + tig*2 + 1) * 4096 + nlo + 8]);
            split2(v0, h0, l0); split2(v1, h1, l1);
            A1[ks*4+1] = (uint32_t)h0 | ((uint32_t)h1 << 16);
            A2[ks*4+1] = (uint32_t)l0 | ((uint32_t)l1 << 16);
            v0 = __ldg(&xb[(size_t)(ks*16 + tig*2 + 8) * 4096 + nlo]);
            v1 = __ldg(&xb[(size_t)(ks*16 + tig*2 + 9) * 4096 + nlo]);
            split2(v0, h0, l0); split2(v1, h1, l1);
            A1[ks*4+2] = (uint32_t)h0 | ((uint32_t)h1 << 16);
            A2[ks*4+2] = (uint32_t)l0 | ((uint32_t)l1 << 16);
            v0 = __ldg(&xb[(size_t)(ks*16 + tig*2 + 8) * 4096 + nlo + 8]);
            v1 = __ldg(&xb[(size_t)(ks*16 + tig*2 + 9) * 4096 + nlo + 8]);
            split2(v0, h0, l0); split2(v1, h1, l1);
            A1[ks*4+3] = (uint32_t)h0 | ((uint32_t)h1 << 16);
            A2[ks*4+3] = (uint32_t)l0 | ((uint32_t)l1 << 16);
        }

        uint32_t K1l = 0xFFFFFFFFu, K2l = 0xFFFFFFFFu, K3l = 0xFFFFFFFFu;
        uint32_t K1h = 0xFFFFFFFFu, K2h = 0xFFFFFFFFu, K3h = 0xFFFFFFFFu;

        // Ping-pong double-buffered B fragments; 2 code-blocks per iteration.
        uint32_t B0h[8], B0l[8], B1h[8], B1l[8];
        ldm4(B0h[0], B0h[1], B0h[2], B0h[3], lmb[0][0]);
        ldm4(B0h[4], B0h[5], B0h[6], B0h[7], lmb[0][1]);
        ldm4(B0l[0], B0l[1], B0l[2], B0l[3], lmb[1][0]);
        ldm4(B0l[4], B0l[5], B0l[6], B0l[7], lmb[1][1]);

        // Consume one 8-code block: 12 MMAs over 3 independent 4-deep chains
        // (D = (1,1), S1 = (2,1), S2 = (1,2)), fold into packed-key top-3.
        #define CONSUME_BLOCK(Bh_, Bl_, NC_) do {                                             \
            float D[4]={0,0,0,0}, S1[4]={0,0,0,0}, S2[4]={0,0,0,0};                           \
            _Pragma("unroll")                                                                 \
            for (int ks = 0; ks < 4; ks++) {                                                  \
                const uint32_t bh0 = Bh_[2*ks], bh1 = Bh_[2*ks+1];                            \
                const uint32_t bl0 = Bl_[2*ks], bl1 = Bl_[2*ks+1];                            \
                mma16816(S1[0],S1[1],S1[2],S1[3], A2[ks*4+0],A2[ks*4+1],A2[ks*4+2],A2[ks*4+3], bh0,bh1); \
                mma16816(D[0],D[1],D[2],D[3],     A1[ks*4+0],A1[ks*4+1],A1[ks*4+2],A1[ks*4+3], bh0,bh1); \
                mma16816(S2[0],S2[1],S2[2],S2[3], A1[ks*4+0],A1[ks*4+1],A1[ks*4+2],A1[ks*4+3], bl0,bl1); \
            }                                                                                 \
            const float2 sv = esqb2[(NC_) * 4 + tig];                                         \
            const uint32_t lc = (uint32_t)(NC_) << 1;                                         \
            uint32_t kk;                                                                      \
            kk = (__float_as_uint(fmaf(-2.0f, D[0] + S1[0] + S2[0], sv.x)) & 0xFFFFFF80u) | lc;       \
            INSK(kk, K1l, K2l, K3l);                                                          \
            kk = (__float_as_uint(fmaf(-2.0f, D[1] + S1[1] + S2[1], sv.y)) & 0xFFFFFF80u) | (lc + 1); \
            INSK(kk, K1l, K2l, K3l);                                                          \
            kk = (__float_as_uint(fmaf(-2.0f, D[2] + S1[2] + S2[2], sv.x)) & 0xFFFFFF80u) | lc;       \
            INSK(kk, K1h, K2h, K3h);                                                          \
            kk = (__float_as_uint(fmaf(-2.0f, D[3] + S1[3] + S2[3], sv.y)) & 0xFFFFFF80u) | (lc + 1); \
            INSK(kk, K1h, K2h, K3h);                                                          \
        } while (0)

        #pragma unroll 1
        for (int nc = 0; nc < 64; nc += 2) {
            // Prefetch block nc+1 into B1 (hides under B0's MMAs).
            {
                const uint32_t co = (uint32_t)(nc + 1) << 10;
                ldm4(B1h[0], B1h[1], B1h[2], B1h[3], lmb[0][0] + co);
                ldm4(B1h[4], B1h[5], B1h[6], B1h[7], lmb[0][1] + co);
                ldm4(B1l[0], B1l[1], B1l[2], B1l[3], lmb[1][0] + co);
                ldm4(B1l[4], B1l[5], B1l[6], B1l[7], lmb[1][1] + co);
            }
            CONSUME_BLOCK(B0h, B0l, nc);
            // Prefetch block nc+2 into B0 (wraps on last iter; harmless).
            {
                const uint32_t co = (uint32_t)((nc + 2) & 63) << 10;
                ldm4(B0h[0], B0h[1], B0h[2], B0h[3], lmb[0][0] + co);
                ldm4(B0h[4], B0h[5], B0h[6], B0h[7], lmb[0][1] + co);
                ldm4(B0l[0], B0l[1], B0l[2], B0l[3], lmb[1][0] + co);
                ldm4(B0l[4], B0l[5], B0l[6], B0l[7], lmb[1][1] + co);
            }
            CONSUME_BLOCK(B1h, B1l, nc + 1);
        }
        #undef CONSUME_BLOCK

        // Epilogue: per row-half (row = rlo + 8*h), reload x, merge, recheck, store.
        #pragma unroll
        for (int h = 0; h < 2; h++) {
            const int row = rlo + 8 * h;
            const int nl  = row & 4095;

            float xr[16];
            #pragma unroll
            for (int ks = 0; ks < 4; ks++) {
                xr[ks*4+0] = __ldg(&xb[(size_t)(ks*16 + tig*2 + 0) * 4096 + nl]);
                xr[ks*4+1] = __ldg(&xb[(size_t)(ks*16 + tig*2 + 1) * 4096 + nl]);
                xr[ks*4+2] = __ldg(&xb[(size_t)(ks*16 + tig*2 + 8) * 4096 + nl]);
                xr[ks*4+3] = __ldg(&xb[(size_t)(ks*16 + tig*2 + 9) * 4096 + nl]);
            }

            float b1, b2, b3; int i1, i2, i3;
            if (h == 0) {
                unpack_key(K1l, tig, b1, i1); unpack_key(K2l, tig, b2, i2);
                unpack_key(K3l, tig, b3, i3);
            } else {
                unpack_key(K1h, tig, b1, i1); unpack_key(K2h, tig, b2, i2);
                unpack_key(K3h, tig, b3, i3);
            }
            MRG3(1, b1, i1, b2, i2, b3, i3);
            MRG3(2, b1, i1, b2, i2, b3, i3);

            const bool tr = (b2 - b1) < GAP_THRESH;
            if (__ballot_sync(0xffffffffu, tr)) {
                const float dA = fmaf(-2.0f, exact_dot(e2p, i1, xr, tig), esqb[i1]);
                const float dB = fmaf(-2.0f, exact_dot(e2p, i2, xr, tig), esqb[i2]);
                const float dC = fmaf(-2.0f, exact_dot(e2p, i3, xr, tig), esqb[i3]);
                int bi = i1; float bd = dA;
                if ((dB < bd) || (dB == bd && i2 < bi)) { bd = dB; bi = i2; }
                if ((dC < bd) || (dC == bd && i3 < bi)) { bd = dC; bi = i3; }
                if (tr) i1 = bi;
            }

            // Straight-through output: out = x + (e - x), fp32.
            const size_t ob = (size_t)row * 32;
            #pragma unroll
            for (int ks = 0; ks < 4; ks++) {
                const float2 e0 = __ldg(&e2p[i1 * 32 + ks * 8 + tig]);
                const float2 e1 = __ldg(&e2p[i1 * 32 + ks * 8 + tig + 4]);
                float2 v;
                v.x = xr[ks*4+0] + (e0.x - xr[ks*4+0]);
                v.y = xr[ks*4+1] + (e0.y - xr[ks*4+1]);
                o2[ob + ks * 8 + tig] = v;
                v.x = xr[ks*4+2] + (e1.x - xr[ks*4+2]);
                v.y = xr[ks*4+3] + (e1.y - xr[ks*4+3]);
                o2[ob + ks * 8 + tig + 4] = v;
            }
        }
    }
}

extern "C" void kernel_launch(void* const* d_in, const int* in_sizes, int n_in,
                              void* d_out, int out_size)
{
    const float* x   = (const float*)d_in[0];
    const float* emb = (const float*)d_in[1];
    float* out = (float*)d_out;

    cudaFuncSetAttribute(vq_mma_kernel,
                         cudaFuncAttributeMaxDynamicSharedMemorySize, SMEM_TOTAL);
    vq_init_kernel<<<1, 1>>>();
    vq_mma_kernel<<<GRIDSZ, THREADS, SMEM_TOTAL>>>(x, emb, out);
}

// round 17
// speedup vs baseline: 1.2887x; 1.1554x over previous
#include <cuda_runtime.h>
#include <cuda_fp16.h>
#include <cstdint>

// VQ nearest-code lookup via mma.sync fp16 2-pass fp32 emulation:
// x = xh + xl (fp16 split, exact residual); cross = (xh + xl) . e_h computed on
// tensor cores; dropped x.e_l term bounded and absorbed by a top-3 exact-fp32
// recheck with a wide gap threshold. Packed-key (IMNMX) top-3 tracking.
// M=16 rows/warp, atomic chunk queue, double-buffered ldmatrix B.
// x:   [32, 64, 64, 64] fp32 -> row r = b*4096 + n; elem (r,c) at x[b*262144 + c*4096 + n]
// emb: [512, 64] fp32
// out: flat [131072, 64] fp32 row-major.

#define THREADS  512
#define NCHUNKS  8192          // 131072 rows / 16 rows per warp-chunk
#define GRIDSZ   148
#define B_TERM   65536         // fp16 codebook term: 512 rows x 128B
#define SM_ESQ   B_TERM
#define SMEM_TOTAL (B_TERM + 2048)
#define BIAS     256.0f
// E_max: |x . e_lo| <= Sum|x| * 2^-11 <= ~0.04 -> distance err <= ~0.08 hard
// (plus 3.9e-3 key truncation). Threshold must exceed 2*E_max: 0.25 gives margin.
#define GAP_THRESH 0.25f

__device__ unsigned int g_chunk_ctr;

__global__ void vq_init_kernel() { g_chunk_ctr = 0u; }

__device__ __forceinline__ uint32_t smem_u32(const void* p) {
    uint32_t a;
    asm("{ .reg .u64 t; cvta.to.shared.u64 t, %1; cvt.u32.u64 %0, t; }" : "=r"(a) : "l"(p));
    return a;
}

__device__ __forceinline__ void mma16816h(float& d0, float& d1, float& d2, float& d3,
                                          uint32_t a0, uint32_t a1, uint32_t a2, uint32_t a3,
                                          uint32_t b0, uint32_t b1) {
    asm("mma.sync.aligned.m16n8k16.row.col.f32.f16.f16.f32 "
        "{%0,%1,%2,%3}, {%4,%5,%6,%7}, {%8,%9}, {%0,%1,%2,%3};"
        : "+f"(d0), "+f"(d1), "+f"(d2), "+f"(d3)
        : "r"(a0), "r"(a1), "r"(a2), "r"(a3), "r"(b0), "r"(b1));
}

__device__ __forceinline__ void ldm4(uint32_t& r0, uint32_t& r1, uint32_t& r2, uint32_t& r3,
                                     uint32_t addr) {
    asm volatile("ldmatrix.sync.aligned.m8n8.x4.shared.b16 {%0,%1,%2,%3}, [%4];"
                 : "=r"(r0), "=r"(r1), "=r"(r2), "=r"(r3) : "r"(addr));
}

// Exact 2-term fp16 split (round-and-subtract residual exact in fp32).
__device__ __forceinline__ void split2h(float v, uint16_t& h, uint16_t& l) {
    __half hh = __float2half_rn(v);
    float r = v - __half2float(hh);
    __half hl = __float2half_rn(r);
    h = __half_as_ushort(hh); l = __half_as_ushort(hl);
}

// Packed-key top-3 insert: pure min/max sorting network (keeps B1<=B2<=B3).
#define INSK(k_, B1_, B2_, B3_) do {                          \
    uint32_t _t1 = max((B1_), (k_)); B1_ = min((B1_), (k_));  \
    uint32_t _t2 = max((B2_), _t1);  B2_ = min((B2_), _t1);   \
    B3_ = min((B3_), _t2);                                    \
} while (0)

// Lexicographic insert (tie -> smaller index), for cross-lane merges.
#define INS3(m_, n_, B1_, I1_, B2_, I2_, B3_, I3_) do {                   \
    bool _l1 = ((m_) < (B1_)) || ((m_) == (B1_) && (n_) < (I1_));         \
    bool _l2 = ((m_) < (B2_)) || ((m_) == (B2_) && (n_) < (I2_));         \
    bool _l3 = ((m_) < (B3_)) || ((m_) == (B3_) && (n_) < (I3_));         \
    B3_ = _l2 ? (B2_) : (_l3 ? (m_) : (B3_));                             \
    I3_ = _l2 ? (I2_) : (_l3 ? (n_) : (I3_));                             \
    B2_ = _l1 ? (B1_) : (_l2 ? (m_) : (B2_));                             \
    I2_ = _l1 ? (I1_) : (_l2 ? (n_) : (I2_));                             \
    B1_ = _l1 ? (m_) : (B1_);                                             \
    I1_ = _l1 ? (n_) : (I1_);                                             \
} while (0)

#define MRG3(off, B1_, I1_, B2_, I2_, B3_, I3_) do {                      \
    float _o1 = __shfl_xor_sync(0xffffffffu, B1_, off);                   \
    int   _j1 = __shfl_xor_sync(0xffffffffu, I1_, off);                   \
    float _o2 = __shfl_xor_sync(0xffffffffu, B2_, off);                   \
    int   _j2 = __shfl_xor_sync(0xffffffffu, I2_, off);                   \
    float _o3 = __shfl_xor_sync(0xffffffffu, B3_, off);                   \
    int   _j3 = __shfl_xor_sync(0xffffffffu, I3_, off);                   \
    INS3(_o1, _j1, B1_, I1_, B2_, I2_, B3_, I3_);                         \
    INS3(_o2, _j2, B1_, I1_, B2_, I2_, B3_, I3_);                         \
    INS3(_o3, _j3, B1_, I1_, B2_, I2_, B3_, I3_);                         \
} while (0)

// Exact fp32 dot of row (xr, 16 vals, mma layout) with code c; quad-reduced.
__device__ __forceinline__ float exact_dot(const float2* __restrict__ e2p,
                                           int c, const float* xr, int tig) {
    float s = 0.0f;
    #pragma unroll
    for (int ks = 0; ks < 4; ks++) {
        float2 e0 = __ldg(&e2p[c * 32 + ks * 8 + tig]);
        float2 e1 = __ldg(&e2p[c * 32 + ks * 8 + tig + 4]);
        s = fmaf(xr[ks*4+0], e0.x, s); s = fmaf(xr[ks*4+1], e0.y, s);
        s = fmaf(xr[ks*4+2], e1.x, s); s = fmaf(xr[ks*4+3], e1.y, s);
    }
    s += __shfl_xor_sync(0xffffffffu, s, 1);
    s += __shfl_xor_sync(0xffffffffu, s, 2);
    return s;
}

// Unpack a packed key: biased truncated value + global code index.
__device__ __forceinline__ void unpack_key(uint32_t key, int tig, float& v, int& n) {
    v = __uint_as_float(key & 0xFFFFFF80u);
    const int l = key & 127;
    n = (l >> 1) * 8 + 2 * tig + (l & 1);
}

__global__ void __launch_bounds__(THREADS, 1)
vq_mma_kernel(const float* __restrict__ x, const float* __restrict__ emb,
              float* __restrict__ out)
{
    extern __shared__ char sm[];
    float* esqb = (float*)(sm + SM_ESQ);      // e_sq + BIAS (exact fp32)
    const float2* esqb2 = (const float2*)esqb;
    const uint32_t sbase = smem_u32(sm);

    const int tid  = threadIdx.x;
    const int lane = tid & 31;
    const int g    = lane >> 2;     // row within 8
    const int tig  = lane & 3;      // thread in group

    // ---- Stage codebook: single fp16 hi term, ldmatrix XOR swizzle ----
    for (int idx = tid; idx < 512 * 64; idx += THREADS) {
        const int n = idx >> 6, k = idx & 63;
        const __half h = __float2half_rn(__ldg(&emb[idx]));
        const uint32_t o = (uint32_t)(n * 128 + ((((k >> 3) ^ (n & 7))) << 4) + ((k & 7) << 1));
        *(uint16_t*)(sm + o) = __half_as_ushort(h);
    }
    for (int n = tid; n < 512; n += THREADS) {
        float s = 0.0f;
        #pragma unroll
        for (int k = 0; k < 64; k++) { float v = __ldg(&emb[n * 64 + k]); s = fmaf(v, v, s); }
        esqb[n] = s + BIAS;
    }
    __syncthreads();

    // ldmatrix base addresses per k-pair p.
    const int l7 = lane & 7, sel = lane >> 3;
    uint32_t lmb[2];
    #pragma unroll
    for (int p = 0; p < 2; p++)
        lmb[p] = sbase + l7 * 128 + (((4 * p + sel) ^ l7) << 4);

    const float2* e2p = (const float2*)emb;
    float2* o2 = (float2*)out;

    // ---- Warp-autonomous chunks from a global atomic queue (no tail) ----
    while (true) {
        unsigned int chunk;
        if (lane == 0) chunk = atomicAdd(&g_chunk_ctr, 1u);
        chunk = __shfl_sync(0xffffffffu, chunk, 0);
        if (chunk >= NCHUNKS) break;

        const int rlo = (int)chunk * 16 + g;            // frag rows: rlo, rlo+8
        const int bb  = rlo >> 12;
        const int nlo = rlo & 4095;
        const float* xb = x + (size_t)bb * 262144;

        // Build A fragments (xh, xl fp16; 4 ksteps x 4 regs); x fp32 not retained.
        uint32_t A1[16], A2[16];
        #pragma unroll
        for (int ks = 0; ks < 4; ks++) {
            uint16_t h0, l0, h1, l1;
            float v0, v1;
            v0 = __ldg(&xb[(size_t)(ks*16 + tig*2 + 0) * 4096 + nlo]);
            v1 = __ldg(&xb[(size_t)(ks*16 + tig*2 + 1) * 4096 + nlo]);
            split2h(v0, h0, l0); split2h(v1, h1, l1);
            A1[ks*4+0] = (uint32_t)h0 | ((uint32_t)h1 << 16);
            A2[ks*4+0] = (uint32_t)l0 | ((uint32_t)l1 << 16);
            v0 = __ldg(&xb[(size_t)(ks*16 + tig*2 + 0) * 4096 + nlo + 8]);
            v1 = __ldg(&xb[(size_t)(ks*16 + tig*2 + 1) * 4096 + nlo + 8]);
            split2h(v0, h0, l0); split2h(v1, h1, l1);
            A1[ks*4+1] = (uint32_t)h0 | ((uint32_t)h1 << 16);
            A2[ks*4+1] = (uint32_t)l0 | ((uint32_t)l1 << 16);
            v0 = __ldg(&xb[(size_t)(ks*16 + tig*2 + 8) * 4096 + nlo]);
            v1 = __ldg(&xb[(size_t)(ks*16 + tig*2 + 9) * 4096 + nlo]);
            split2h(v0, h0, l0); split2h(v1, h1, l1);
            A1[ks*4+2] = (uint32_t)h0 | ((uint32_t)h1 << 16);
            A2[ks*4+2] = (uint32_t)l0 | ((uint32_t)l1 << 16);
            v0 = __ldg(&xb[(size_t)(ks*16 + tig*2 + 8) * 4096 + nlo + 8]);
            v1 = __ldg(&xb[(size_t)(ks*16 + tig*2 + 9) * 4096 + nlo + 8]);
            split2h(v0, h0, l0); split2h(v1, h1, l1);
            A1[ks*4+3] = (uint32_t)h0 | ((uint32_t)h1 << 16);
            A2[ks*4+3] = (uint32_t)l0 | ((uint32_t)l1 << 16);
        }

        uint32_t K1l = 0xFFFFFFFFu, K2l = 0xFFFFFFFFu, K3l = 0xFFFFFFFFu;
        uint32_t K1h = 0xFFFFFFFFu, K2h = 0xFFFFFFFFu, K3h = 0xFFFFFFFFu;

        // Ping-pong double-buffered B fragments; 2 code-blocks per iteration.
        uint32_t B0[8], B1[8];
        ldm4(B0[0], B0[1], B0[2], B0[3], lmb[0]);
        ldm4(B0[4], B0[5], B0[6], B0[7], lmb[1]);

        // Consume one 8-code block: 8 MMAs over 2 independent 4-deep chains
        // (D = xh.eh, S = xl.eh), fold into packed-key top-3.
        #define CONSUME_BLOCK(B_, NC_) do {                                                   \
            float D[4]={0,0,0,0}, S[4]={0,0,0,0};                                             \
            _Pragma("unroll")                                                                 \
            for (int ks = 0; ks < 4; ks++) {                                                  \
                const uint32_t b0 = B_[2*ks], b1 = B_[2*ks+1];                                \
                mma16816h(S[0],S[1],S[2],S[3], A2[ks*4+0],A2[ks*4+1],A2[ks*4+2],A2[ks*4+3], b0,b1); \
                mma16816h(D[0],D[1],D[2],D[3], A1[ks*4+0],A1[ks*4+1],A1[ks*4+2],A1[ks*4+3], b0,b1); \
            }                                                                                 \
            const float2 sv = esqb2[(NC_) * 4 + tig];                                         \
            const uint32_t lc = (uint32_t)(NC_) << 1;                                         \
            uint32_t kk;                                                                      \
            kk = (__float_as_uint(fmaf(-2.0f, D[0] + S[0], sv.x)) & 0xFFFFFF80u) | lc;        \
            INSK(kk, K1l, K2l, K3l);                                                          \
            kk = (__float_as_uint(fmaf(-2.0f, D[1] + S[1], sv.y)) & 0xFFFFFF80u) | (lc + 1);  \
            INSK(kk, K1l, K2l, K3l);                                                          \
            kk = (__float_as_uint(fmaf(-2.0f, D[2] + S[2], sv.x)) & 0xFFFFFF80u) | lc;        \
            INSK(kk, K1h, K2h, K3h);                                                          \
            kk = (__float_as_uint(fmaf(-2.0f, D[3] + S[3], sv.y)) & 0xFFFFFF80u) | (lc + 1);  \
            INSK(kk, K1h, K2h, K3h);                                                          \
        } while (0)

        #pragma unroll 1
        for (int nc = 0; nc < 64; nc += 2) {
            // Prefetch block nc+1 into B1 (hides under B0's MMAs).
            {
                const uint32_t co = (uint32_t)(nc + 1) << 10;
                ldm4(B1[0], B1[1], B1[2], B1[3], lmb[0] + co);
                ldm4(B1[4], B1[5], B1[6], B1[7], lmb[1] + co);
            }
            CONSUME_BLOCK(B0, nc);
            // Prefetch block nc+2 into B0 (wraps on last iter; harmless).
            {
                const uint32_t co = (uint32_t)((nc + 2) & 63) << 10;
                ldm4(B0[0], B0[1], B0[2], B0[3], lmb[0] + co);
                ldm4(B0[4], B0[5], B0[6], B0[7], lmb[1] + co);
            }
            CONSUME_BLOCK(B1, nc + 1);
        }
        #undef CONSUME_BLOCK

        // Epilogue: per row-half (row = rlo + 8*h), reload x, merge, recheck, store.
        #pragma unroll
        for (int h = 0; h < 2; h++) {
            const int row = rlo + 8 * h;
            const int nl  = row & 4095;

            float xr[16];
            #pragma unroll
            for (int ks = 0; ks < 4; ks++) {
                xr[ks*4+0] = __ldg(&xb[(size_t)(ks*16 + tig*2 + 0) * 4096 + nl]);
                xr[ks*4+1] = __ldg(&xb[(size_t)(ks*16 + tig*2 + 1) * 4096 + nl]);
                xr[ks*4+2] = __ldg(&xb[(size_t)(ks*16 + tig*2 + 8) * 4096 + nl]);
                xr[ks*4+3] = __ldg(&xb[(size_t)(ks*16 + tig*2 + 9) * 4096 + nl]);
            }

            float b1, b2, b3; int i1, i2, i3;
            if (h == 0) {
                unpack_key(K1l, tig, b1, i1); unpack_key(K2l, tig, b2, i2);
                unpack_key(K3l, tig, b3, i3);
            } else {
                unpack_key(K1h, tig, b1, i1); unpack_key(K2h, tig, b2, i2);
                unpack_key(K3h, tig, b3, i3);
            }
            MRG3(1, b1, i1, b2, i2, b3, i3);
            MRG3(2, b1, i1, b2, i2, b3, i3);

            const bool tr = (b2 - b1) < GAP_THRESH;
            if (__ballot_sync(0xffffffffu, tr)) {
                const float dA = fmaf(-2.0f, exact_dot(e2p, i1, xr, tig), esqb[i1]);
                const float dB = fmaf(-2.0f, exact_dot(e2p, i2, xr, tig), esqb[i2]);
                const float dC = fmaf(-2.0f, exact_dot(e2p, i3, xr, tig), esqb[i3]);
                int bi = i1; float bd = dA;
                if ((dB < bd) || (dB == bd && i2 < bi)) { bd = dB; bi = i2; }
                if ((dC < bd) || (dC == bd && i3 < bi)) { bd = dC; bi = i3; }
                if (tr) i1 = bi;
            }

            // Straight-through output: out = x + (e - x), fp32.
            const size_t ob = (size_t)row * 32;
            #pragma unroll
            for (int ks = 0; ks < 4; ks++) {
                const float2 e0 = __ldg(&e2p[i1 * 32 + ks * 8 + tig]);
                const float2 e1 = __ldg(&e2p[i1 * 32 + ks * 8 + tig + 4]);
                float2 v;
                v.x = xr[ks*4+0] + (e0.x - xr[ks*4+0]);
                v.y = xr[ks*4+1] + (e0.y - xr[ks*4+1]);
                o2[ob + ks * 8 + tig] = v;
                v.x = xr[ks*4+2] + (e1.x - xr[ks*4+2]);
                v.y = xr[ks*4+3] + (e1.y - xr[ks*4+3]);
                o2[ob + ks * 8 + tig + 4] = v;
            }
        }
    }
}

extern "C" void kernel_launch(void* const* d_in, const int* in_sizes, int n_in,
                              void* d_out, int out_size)
{
    const float* x   = (const float*)d_in[0];
    const float* emb = (const float*)d_in[1];
    float* out = (float*)d_out;

    cudaFuncSetAttribute(vq_mma_kernel,
                         cudaFuncAttributeMaxDynamicSharedMemorySize, SMEM_TOTAL);
    vq_init_kernel<<<1, 1>>>();
    vq_mma_kernel<<<GRIDSZ, THREADS, SMEM_TOTAL>>>(x, emb, out);
}